// round 15
// baseline (speedup 1.0000x reference)
#include <cuda_runtime.h>
#include <cuda_fp16.h>
#include <math.h>
#include <stdint.h>

#define HD 128
#define NMAX 100000
#define EMAX 1600000

// ================= scratch =================
__device__ __align__(16) __half g_tf[(size_t)NMAX * HD];
__device__ __align__(16) __half g_sf[(size_t)NMAX * HD];
__device__ float g_dinv[NMAX];
__device__ int   g_deg[NMAX];
__device__ int   g_off[NMAX];
__device__ int   g_cur[NMAX];
__device__ int   g_csr[EMAX];
__device__ int   g_base;                                // scan ticket counter
__device__ float g_gb[3 * HD];                          // gate biases (i,g,o)
__device__ __align__(16) __half g_wf[6 * HD * HD];      // fp16 weight planes [n][k]
// 0,1,2 = W_ih gate blocks (i,g,o); 3 = W1^T; 4 = W2^T; 5 = W3

__device__ __forceinline__ uint32_t smem_u32(const void* p) {
    uint32_t a;
    asm("{ .reg .u64 t; cvta.to.shared.u64 t, %1; cvt.u32.u64 %0, t; }" : "=r"(a) : "l"(p));
    return a;
}
#define LDSM4(r, addr) \
    asm volatile("ldmatrix.sync.aligned.m8n8.x4.shared.b16 {%0,%1,%2,%3}, [%4];" \
        : "=r"((r)[0]), "=r"((r)[1]), "=r"((r)[2]), "=r"((r)[3]) : "r"(addr))

__device__ __forceinline__ void mma_f16(float* d, const uint32_t* a, const uint32_t* b) {
    asm volatile(
        "mma.sync.aligned.m16n8k16.row.col.f32.f16.f16.f32 "
        "{%0,%1,%2,%3}, {%4,%5,%6,%7}, {%8,%9}, {%0,%1,%2,%3};"
        : "+f"(d[0]), "+f"(d[1]), "+f"(d[2]), "+f"(d[3])
        : "r"(a[0]), "r"(a[1]), "r"(a[2]), "r"(a[3]), "r"(b[0]), "r"(b[1]));
}

// fast activations: MUFU-based, rel err ~2^-21
__device__ __forceinline__ float fsig(float x)  { return __fdividef(1.0f, 1.0f + __expf(-x)); }
__device__ __forceinline__ float ftanh(float x) { return __fdividef(2.0f, 1.0f + __expf(-2.0f * x)) - 1.0f; }

// ================= prep: weights -> fp16; zero deg + ticket =================
__global__ void prep_zero(const float* __restrict__ Wih,
                          const float* __restrict__ W1,
                          const float* __restrict__ W2,
                          const float* __restrict__ W3,
                          const float* __restrict__ bih,
                          const float* __restrict__ bhh, int n) {
    int idx = blockIdx.x * blockDim.x + threadIdx.x;
    if (idx == 0) g_base = 0;
    if (idx < n) g_deg[idx] = 0;
    if (idx < HD * HD) {
        int nn = idx >> 7, kk = idx & 127;
        const int G[3] = {0, 256, 384};
        g_wf[0 * 16384 + idx] = __float2half_rn(Wih[(G[0] + nn) * HD + kk]);
        g_wf[1 * 16384 + idx] = __float2half_rn(Wih[(G[1] + nn) * HD + kk]);
        g_wf[2 * 16384 + idx] = __float2half_rn(Wih[(G[2] + nn) * HD + kk]);
        g_wf[3 * 16384 + idx] = __float2half_rn(W1[kk * HD + nn]);
        g_wf[4 * 16384 + idx] = __float2half_rn(W2[kk * HD + nn]);
        g_wf[5 * 16384 + idx] = __float2half_rn(W3[nn * HD + kk]);
        if (idx < 3 * HD) {
            int p = idx / HD, j = idx % HD;
            g_gb[idx] = bih[G[p] + j] + bhh[G[p] + j];
        }
    }
}

// ================= degree / single-pass scan / CSR =================
__global__ void deg_count(const int* __restrict__ ei, int e) {
    int i = blockIdx.x * blockDim.x + threadIdx.x;
    if (i < e) atomicAdd(&g_deg[ei[e + i]], 1);
}
__global__ void scan_k(int n) {
    __shared__ int sm[1024];
    __shared__ int sbase;
    int t = threadIdx.x, i = blockIdx.x * 1024 + t;
    int v = (i < n) ? g_deg[i] : 0;
    if (i < n) g_dinv[i] = rsqrtf((float)v + 1.0f);
    sm[t] = v; __syncthreads();
    for (int o = 1; o < 1024; o <<= 1) {
        int tmp = (t >= o) ? sm[t - o] : 0; __syncthreads();
        sm[t] += tmp; __syncthreads();
    }
    if (t == 1023) sbase = atomicAdd(&g_base, sm[1023]);
    __syncthreads();
    if (i < n) {
        int o = sm[t] - v + sbase;
        g_off[i] = o; g_cur[i] = o;
    }
}
__global__ void csr_fill(const int* __restrict__ ei, int e) {
    int i = blockIdx.x * blockDim.x + threadIdx.x;
    if (i < e) {
        int d = ei[e + i];
        g_csr[atomicAdd(&g_cur[d], 1)] = ei[i];
    }
}

// ================= fused LSTM + conv1 transform (UNscaled t) =================
// planes 0-2: gates -> h (registers); plane 3: t = h @ W1 -> g_tf (no dinv)
#define ASTR 272
#define L_A   0           // 64  x 272 = 17408
#define L_B   17408       // 128 x 272 = 34816
#define L_TOT 52224

__global__ void __launch_bounds__(256, 3)
lstm_fused(const float* __restrict__ z, __half* __restrict__ tout, int n) {
    extern __shared__ char sm[];
    uint32_t sbase = smem_u32(sm);
    int tid = threadIdx.x, lane = tid & 31, wid = tid >> 5;
    int gid = lane >> 2, tig = lane & 3;
    int wm = wid >> 2, wn = wid & 3;            // 2 m x 4 n warps
    int r0 = blockIdx.x * 64;

    // ---- load z (fp32) -> fp16 A (64 x 128) ----
    for (int i = tid; i < 64 * 16; i += 256) {
        int row = i >> 4, q = i & 15;
        float4 v1 = make_float4(0.f, 0.f, 0.f, 0.f), v2 = v1;
        if (r0 + row < n) {
            v1 = *(const float4*)(z + (size_t)(r0 + row) * HD + q * 8);
            v2 = *(const float4*)(z + (size_t)(r0 + row) * HD + q * 8 + 4);
        }
        __half2 h0 = __float22half2_rn(make_float2(v1.x, v1.y));
        __half2 h1 = __float22half2_rn(make_float2(v1.z, v1.w));
        __half2 h2 = __float22half2_rn(make_float2(v2.x, v2.y));
        __half2 h3 = __float22half2_rn(make_float2(v2.z, v2.w));
        uint4 u = make_uint4(*(uint32_t*)&h0, *(uint32_t*)&h1, *(uint32_t*)&h2, *(uint32_t*)&h3);
        *(uint4*)(sm + L_A + row * ASTR + q * 16) = u;
    }

    uint32_t aAl = (uint32_t)((wm * 32 + (lane & 15)) * ASTR + ((lane >> 4) << 3) * 2);
    uint32_t aBl = (uint32_t)((wn * 32 + ((lane >> 4) << 3) + (lane & 7)) * ASTR
                              + ((lane >> 3) & 1) * 16);

    float cp[2][4][4];
    float acc[2][4][4];

#pragma unroll 1
    for (int p = 0; p < 4; p++) {
        __syncthreads();
        if (p == 3) {
            // h (registers) -> A buffer as fp16
#pragma unroll
            for (int mt = 0; mt < 2; mt++) {
#pragma unroll
                for (int nt = 0; nt < 4; nt++) {
                    int col = wn * 32 + nt * 8 + tig * 2;
                    int ra = wm * 32 + mt * 16 + gid;
                    __half2 v0 = __float22half2_rn(make_float2(cp[mt][nt][0], cp[mt][nt][1]));
                    __half2 v1 = __float22half2_rn(make_float2(cp[mt][nt][2], cp[mt][nt][3]));
                    *(uint32_t*)(sm + L_A + ra * ASTR + col * 2) = *(uint32_t*)&v0;
                    *(uint32_t*)(sm + L_A + (ra + 8) * ASTR + col * 2) = *(uint32_t*)&v1;
                }
            }
        }
        for (int i = tid; i < 128 * 16; i += 256) {
            int row = i >> 4, q = i & 15;
            uint4 h = __ldg((const uint4*)(g_wf + (size_t)p * 16384 + row * HD + q * 8));
            *(uint4*)(sm + L_B + row * ASTR + q * 16) = h;
        }
        __syncthreads();

#pragma unroll
        for (int mt = 0; mt < 2; mt++)
#pragma unroll
            for (int nt = 0; nt < 4; nt++)
#pragma unroll
                for (int q = 0; q < 4; q++) acc[mt][nt][q] = 0.0f;

        uint32_t Ab = sbase + L_A + aAl;
        uint32_t Bb = sbase + L_B + aBl;
#pragma unroll
        for (int ks = 0; ks < 8; ks++) {
            uint32_t ra0[4], ra1[4], rb0[4], rb1[4];
            LDSM4(ra0, Ab + ks * 32);
            LDSM4(ra1, Ab + 16 * ASTR + ks * 32);
            LDSM4(rb0, Bb + ks * 32);
            LDSM4(rb1, Bb + 16 * ASTR + ks * 32);
            mma_f16(acc[0][0], ra0, rb0 + 0);
            mma_f16(acc[0][1], ra0, rb0 + 2);
            mma_f16(acc[0][2], ra0, rb1 + 0);
            mma_f16(acc[0][3], ra0, rb1 + 2);
            mma_f16(acc[1][0], ra1, rb0 + 0);
            mma_f16(acc[1][1], ra1, rb0 + 2);
            mma_f16(acc[1][2], ra1, rb1 + 0);
            mma_f16(acc[1][3], ra1, rb1 + 2);
        }

        if (p < 3) {
#pragma unroll
            for (int mt = 0; mt < 2; mt++) {
#pragma unroll
                for (int nt = 0; nt < 4; nt++) {
                    int col = wn * 32 + nt * 8 + tig * 2;
                    float2 bg = *(const float2*)(g_gb + p * HD + col);
#pragma unroll
                    for (int q = 0; q < 4; q++) {
                        float gv = acc[mt][nt][q] + ((q & 1) ? bg.y : bg.x);
                        if (p == 0)      cp[mt][nt][q] = fsig(gv);
                        else if (p == 1) cp[mt][nt][q] = cp[mt][nt][q] * ftanh(gv);
                        else             cp[mt][nt][q] = fsig(gv) * ftanh(cp[mt][nt][q]);
                    }
                }
            }
        } else {
            // conv1-transform epilogue: t = acc (unscaled) -> gmem fp16
#pragma unroll
            for (int mt = 0; mt < 2; mt++) {
                int row0 = r0 + wm * 32 + mt * 16 + gid;
                int row1 = row0 + 8;
#pragma unroll
                for (int nt = 0; nt < 4; nt++) {
                    int col = wn * 32 + nt * 8 + tig * 2;
                    __half2 v0 = __float22half2_rn(make_float2(acc[mt][nt][0], acc[mt][nt][1]));
                    __half2 v1 = __float22half2_rn(make_float2(acc[mt][nt][2], acc[mt][nt][3]));
                    if (row0 < n) *(uint32_t*)(tout + (size_t)row0 * HD + col) = *(uint32_t*)&v0;
                    if (row1 < n) *(uint32_t*)(tout + (size_t)row1 * HD + col) = *(uint32_t*)&v1;
                }
            }
        }
    }
}

// ================= mma GEMM, full-K resident, single fp16 =================
// MODE 1: t = acc -> fp16 C16 (unscaled);  MODE 2: out = relu(acc + bias[col]) -> fp32
#define G_A   0
#define G_B   34816
#define SMEM_G 69632

template <int MODE>
__global__ void __launch_bounds__(256, 2)
mma_gemm(const __half* __restrict__ A, const __half* __restrict__ Bp,
         const float* __restrict__ bias,
         __half* __restrict__ C16, float* __restrict__ C32, int n) {
    extern __shared__ char sm[];
    uint32_t sbase = smem_u32(sm);

    int tid = threadIdx.x, lane = tid & 31, wid = tid >> 5;
    int gid = lane >> 2, tig = lane & 3;
    int wm = wid & 3, wn = wid >> 2;
    int r0 = blockIdx.x * 128;

    uint32_t aAl = (uint32_t)((wm * 32 + (lane & 15)) * ASTR + ((lane >> 4) << 3) * 2);
    uint32_t aBl = (uint32_t)((wn * 64 + ((lane >> 4) << 3) + (lane & 7)) * ASTR
                              + ((lane >> 3) & 1) * 16);

    float acc[2][8][4];
#pragma unroll
    for (int mt = 0; mt < 2; mt++)
#pragma unroll
        for (int nt = 0; nt < 8; nt++)
#pragma unroll
            for (int q = 0; q < 4; q++) acc[mt][nt][q] = 0.0f;

    for (int i = tid; i < 128 * 16; i += 256) {
        int row = i >> 4, q = i & 15;
        uint4 u = make_uint4(0u, 0u, 0u, 0u);
        if (r0 + row < n)
            u = *(const uint4*)(A + (size_t)(r0 + row) * HD + q * 8);
        *(uint4*)(sm + G_A + row * ASTR + q * 16) = u;
        uint4 h = __ldg((const uint4*)(Bp + (size_t)row * HD + q * 8));
        *(uint4*)(sm + G_B + row * ASTR + q * 16) = h;
    }
    __syncthreads();

#pragma unroll
    for (int ks = 0; ks < 8; ks++) {
        uint32_t ra0[4], ra1[4];
        LDSM4(ra0, sbase + G_A + aAl + ks * 32);
        LDSM4(ra1, sbase + G_A + aAl + 16 * ASTR + ks * 32);
#pragma unroll
        for (int nt2 = 0; nt2 < 4; nt2++) {
            uint32_t rb[4];
            LDSM4(rb, sbase + G_B + aBl + nt2 * 16 * ASTR + ks * 32);
            mma_f16(acc[0][nt2 * 2 + 0], ra0, rb + 0);
            mma_f16(acc[0][nt2 * 2 + 1], ra0, rb + 2);
            mma_f16(acc[1][nt2 * 2 + 0], ra1, rb + 0);
            mma_f16(acc[1][nt2 * 2 + 1], ra1, rb + 2);
        }
    }

#pragma unroll
    for (int mt = 0; mt < 2; mt++) {
        int row0 = r0 + wm * 32 + mt * 16 + gid;
        int row1 = row0 + 8;
#pragma unroll
        for (int nt = 0; nt < 8; nt++) {
            int col = wn * 64 + nt * 8 + tig * 2;
            float d0 = acc[mt][nt][0], d1 = acc[mt][nt][1];
            float d2 = acc[mt][nt][2], d3 = acc[mt][nt][3];
            if (MODE == 1) {
                __half2 v0 = __float22half2_rn(make_float2(d0, d1));
                __half2 v1 = __float22half2_rn(make_float2(d2, d3));
                if (row0 < n) *(uint32_t*)(C16 + (size_t)row0 * HD + col) = *(uint32_t*)&v0;
                if (row1 < n) *(uint32_t*)(C16 + (size_t)row1 * HD + col) = *(uint32_t*)&v1;
            } else {
                float b0 = __ldg(bias + col), b1 = __ldg(bias + col + 1);
                if (row0 < n) *(float2*)(C32 + (size_t)row0 * HD + col) =
                    make_float2(fmaxf(d0 + b0, 0.f), fmaxf(d1 + b1, 0.f));
                if (row1 < n) *(float2*)(C32 + (size_t)row1 * HD + col) =
                    make_float2(fmaxf(d2 + b0, 0.f), fmaxf(d3 + b1, 0.f));
            }
        }
    }
}

// ================= CSR aggregation, per-edge dinv[src] scaling =================
// out[w] = fp16( dinv[w]*(dinv[w]*t[w] + sum_e dinv[src]*t[src]) + bias )
template <bool RELU>
__global__ void aggregate_k(const __half* __restrict__ t2,
                            const float* __restrict__ bias,
                            __half* __restrict__ out, int n) {
    int w = (blockIdx.x * blockDim.x + threadIdx.x) >> 5;
    int lane = threadIdx.x & 31;
    if (w >= n) return;
    float dvv = g_dinv[w];
    const uint2* T = (const uint2*)t2;
    uint2 self = T[(size_t)w * 32 + lane];
    float2 a0 = __half22float2(*(__half2*)&self.x);
    float2 a1 = __half22float2(*(__half2*)&self.y);
    float4 acc = make_float4(a0.x * dvv, a0.y * dvv, a1.x * dvv, a1.y * dvv);
    const int* idx = g_csr + g_off[w];
    int cnt = g_deg[w];
    int i = 0;
    for (; i + 7 < cnt; i += 8) {
        int ix[8];
#pragma unroll
        for (int u = 0; u < 8; u++) ix[u] = idx[i + u];
        uint2 v[8];
        float ds[8];
#pragma unroll
        for (int u = 0; u < 8; u++) {
            v[u] = T[(size_t)ix[u] * 32 + lane];
            ds[u] = __ldg(g_dinv + ix[u]);         // lane-uniform broadcast
        }
#pragma unroll
        for (int u = 0; u < 8; u++) {
            float2 f0 = __half22float2(*(__half2*)&v[u].x);
            float2 f1 = __half22float2(*(__half2*)&v[u].y);
            acc.x += f0.x * ds[u]; acc.y += f0.y * ds[u];
            acc.z += f1.x * ds[u]; acc.w += f1.y * ds[u];
        }
    }
    for (; i < cnt; i++) {
        int s = idx[i];
        uint2 v = T[(size_t)s * 32 + lane];
        float dsv = __ldg(g_dinv + s);
        float2 f0 = __half22float2(*(__half2*)&v.x);
        float2 f1 = __half22float2(*(__half2*)&v.y);
        acc.x += f0.x * dsv; acc.y += f0.y * dsv;
        acc.z += f1.x * dsv; acc.w += f1.y * dsv;
    }
    float4 b4 = ((const float4*)bias)[lane];
    float o0 = acc.x * dvv + b4.x, o1 = acc.y * dvv + b4.y;
    float o2 = acc.z * dvv + b4.z, o3 = acc.w * dvv + b4.w;
    if (RELU) {
        o0 = fmaxf(o0, 0.f); o1 = fmaxf(o1, 0.f);
        o2 = fmaxf(o2, 0.f); o3 = fmaxf(o3, 0.f);
    }
    __half2 h0 = __float22half2_rn(make_float2(o0, o1));
    __half2 h1 = __float22half2_rn(make_float2(o2, o3));
    uint2 o = make_uint2(*(uint32_t*)&h0, *(uint32_t*)&h1);
    ((uint2*)out)[(size_t)w * 32 + lane] = o;
}

// ================= launch (dual-stream fork inside graph capture) =================
extern "C" void kernel_launch(void* const* d_in, const int* in_sizes, int n_in,
                              void* d_out, int out_size) {
    const float* z   = (const float*)d_in[0];
    const int*   ei  = (const int*)d_in[1];
    const float* Wih = (const float*)d_in[2];
    const float* bih = (const float*)d_in[4];
    const float* bhh = (const float*)d_in[5];
    const float* W1  = (const float*)d_in[6];
    const float* b1  = (const float*)d_in[7];
    const float* W2  = (const float*)d_in[8];
    const float* b2  = (const float*)d_in[9];
    const float* W3  = (const float*)d_in[10];
    const float* b3  = (const float*)d_in[11];

    int n = in_sizes[0] / HD;
    int e = in_sizes[1] / 2;
    float* out = (float*)d_out;

    __half *p_tf, *p_sf, *p_wf;
    cudaGetSymbolAddress((void**)&p_tf, g_tf);
    cudaGetSymbolAddress((void**)&p_sf, g_sf);
    cudaGetSymbolAddress((void**)&p_wf, g_wf);

    cudaFuncSetAttribute(lstm_fused, cudaFuncAttributeMaxDynamicSharedMemorySize, L_TOT);
    cudaFuncSetAttribute(mma_gemm<1>, cudaFuncAttributeMaxDynamicSharedMemorySize, SMEM_G);
    cudaFuncSetAttribute(mma_gemm<2>, cudaFuncAttributeMaxDynamicSharedMemorySize, SMEM_G);

    // side stream + events, created once (identical work per call — determinism holds)
    static cudaStream_t s1 = nullptr;
    static cudaEvent_t evA = nullptr, evB = nullptr;
    if (!s1) {
        cudaStreamCreate(&s1);
        cudaEventCreateWithFlags(&evA, cudaEventDisableTiming);
        cudaEventCreateWithFlags(&evB, cudaEventDisableTiming);
    }

    int nb = (n + 1023) / 1024;
    // main: prep -> lstm -> (join) -> agg1 -> gemm2 -> agg2 -> final
    // side: deg_count -> scan -> csr_fill   (hidden under lstm)
    prep_zero<<<(n + 255) / 256, 256>>>(Wih, W1, W2, W3, bih, bhh, n);
    cudaEventRecord(evA, 0);
    cudaStreamWaitEvent(s1, evA, 0);
    deg_count<<<(e + 255) / 256, 256, 0, s1>>>(ei, e);
    scan_k<<<nb, 1024, 0, s1>>>(n);
    csr_fill<<<(e + 255) / 256, 256, 0, s1>>>(ei, e);
    cudaEventRecord(evB, s1);

    lstm_fused<<<(n + 63) / 64, 256, L_TOT>>>(z, p_tf, n);
    cudaStreamWaitEvent(0, evB, 0);

    dim3 gg((n + 127) / 128);
    // conv1 aggregate + fused relu
    aggregate_k<true><<<((size_t)n * 32 + 255) / 256, 256>>>(p_tf, b1, p_sf, n);
    // conv2 transform: t = s @ W2 (unscaled)
    mma_gemm<1><<<gg, 256, SMEM_G>>>(p_sf, p_wf + 4 * 16384, nullptr, p_tf, nullptr, n);
    aggregate_k<false><<<((size_t)n * 32 + 255) / 256, 256>>>(p_tf, b2, p_sf, n);
    // final: out = relu(s @ W3^T + b3)
    mma_gemm<2><<<gg, 256, SMEM_G>>>(p_sf, p_wf + 5 * 16384, b3, nullptr, out, n);
}